// round 2
// baseline (speedup 1.0000x reference)
#include <cuda_runtime.h>

// SRLEmbeddings: B=16,S=32,L=256,D=768,P=16,T=4, PAD=1
// Grid: (b*s, dsplit) flattened: blockIdx.x = bs*4 + split, 2048 CTAs.
// Block: 192 threads; thread t owns float4 column group at d = split*192 + t*4.

#define NB 16
#define NS 32
#define NL 256
#define ND 768
#define NP 16
#define NT 4
#define NPAIR 48
#define PAD_ID 1
#define NSPLIT 4
#define DCOLS (ND / NSPLIT)        // 192 columns per CTA
#define NTHREADS (DCOLS / 4)       // 192? no: 192/4 = 48... use 192 threads, see below

// We use 192 threads: thread t owns one float4 (4 columns) => covers 768/4=192
// float4 groups total across 4 splits; per CTA that's 48 float4 groups... we
// instead keep 192 threads and have each thread own ONE float4 of the CTA's
// 192-column slice => 48 float4 groups need only 48 threads. To keep enough
// warps, each CTA instead covers 192 columns with 48 float4 groups handled by
// 192 threads as 4 row-interleaved groups? Simpler: block=192, thread t owns
// float4 group (t % 48), row subset (t / 48). That splits acc ownership across
// rows -> conflicts. FINAL CHOICE: block = 192 threads, CTA covers the FULL
// 192-column slice with each thread owning 1 column? No vectorization then.
//
// Clean resolution: CTA covers 192 columns; 48 float4 groups; block = 48*4=192
// threads arranged as (rowlane r = t/48 in 0..3, col group c = t%48). Each
// thread processes rows l with (l % 4 == r). acc is privatized per rowlane:
// acc[4][NPAIR][48] float4 would be 4x36.9KB -> too big. Instead acc is
// indexed [NPAIR][48] float4 and each (pair,c) cell is touched by 4 rowlane
// threads -> use per-rowlane register partial? pairs vary per row... So we
// DROP row interleaving: block = 48 threads is too small.
//
// => Use 2-way D split instead: CTA covers 384 columns = 96 float4 groups,
// block = 96 threads? Still small. Use float2: CTA covers 384 cols, block =
// 192 threads, each owns one float2 (LDG.64). Compromise: LDG.64 with 2 CTAs
// of this size per... Let's just do: NSPLIT=4, block=192, each thread owns
// ONE float4 group but there are only 48 groups -> threads 48..191 idle. BAD.
//
// Actual implementation below: NSPLIT=2, block=192, each thread owns one
// float2 -> no. See final constants:

#undef NSPLIT
#undef DCOLS
#undef NTHREADS
#define NSPLIT 4
#define DCOLS 192                  // columns per CTA
#define NF4 (DCOLS / 4)            // 48 float4 groups
#define NTHREADS 192               // 4 row-lanes x 48 col groups

// smem per CTA:
//   acc    : 4 rowlanes * NPAIR * NF4 float4?? too big. We instead keep
//            acc[NPAIR][DCOLS] floats = 48*192*4 = 36864 and have each thread
//            own 1 SCALAR column for accumulation while LOADING as float4 and
//            exchanging via shuffle? Complexity not worth it.
//
// FINAL DESIGN (the one actually compiled):
//   block = 192 threads, thread t owns scalar column t of the 192-col slice,
//   but loads are float4 done cooperatively: per 8-row batch, the 192 threads
//   issue 48 float4 x 8 rows = 384 LDG.128 (2 per thread), covering the
//   8x192 subtile, staged to registers, then redistributed via shared staging
//   buffer (8*192*4 = 6KB) with no bank conflicts. This keeps LDG.128 (MLP up)
//   and scalar acc ownership (no conflicts).

#define SMEM_ACC    (NPAIR * DCOLS * 4)   // 36864
#define SMEM_STAGE  (8 * DCOLS * 4)       // 6144
#define SMEM_CNT    (NPAIR * NL)          // 12288
#define SMEM_RM     (NL * 8)              // 2048
#define SMEM_SID    (NL * 4)              // 1024
#define SMEM_AF     (NL * 4)              // 1024
#define SMEM_SPAN   (NPAIR * NT * 4)      // 768
#define SMEM_DEN    (NPAIR * 4 + 16)      // 208
#define SMEM_BYTES  (SMEM_ACC + SMEM_STAGE + SMEM_CNT + SMEM_RM + SMEM_SID + SMEM_AF + SMEM_SPAN + SMEM_DEN)

__global__ __launch_bounds__(NTHREADS, 4)
void srl_kernel(const int* __restrict__ sent_ids,
                const int* __restrict__ attn,
                const int* __restrict__ pred_ids,
                const int* __restrict__ arg0_ids,
                const int* __restrict__ arg1_ids,
                const float* __restrict__ emb,
                float* __restrict__ out)
{
    extern __shared__ char smem_raw[];
    float*         acc    = (float*)smem_raw;                        // [NPAIR][DCOLS]
    float*         stage  = acc + NPAIR * DCOLS;                     // [8][DCOLS]
    unsigned char* cnt_s  = (unsigned char*)(stage + 8 * DCOLS);     // [NPAIR][NL]
    unsigned*      rm     = (unsigned*)(cnt_s + NPAIR * NL);         // [NL][2]
    int*           sid_s  = (int*)(rm + 2 * NL);                     // [NL]
    float*         af     = (float*)(sid_s + NL);                    // [NL]
    int*           span_s = (int*)(af + NL);                         // [NPAIR][NT]
    int*           den_s  = (int*)(span_s + NPAIR * NT);             // [NPAIR]
    int*           tokcnt = den_s + NPAIR;

    const int blk   = blockIdx.x;
    const int bs    = blk >> 2;            // (b*S+s)
    const int split = blk & 3;             // which 192-col slice
    const int tid   = threadIdx.x;         // 0..191
    const int dbase = split * DCOLS;       // column offset of this CTA

    // ---- init ----
    #pragma unroll
    for (int i = 0; i < NPAIR; i++) acc[i * DCOLS + tid] = 0.0f;
    if (tid < NPAIR) den_s[tid] = 0;
    if (tid == 0)    tokcnt[0]  = 0;

    // ---- load per-(b,s) metadata ----
    for (int l = tid; l < NL; l += NTHREADS) {
        sid_s[l] = sent_ids[bs * NL + l];
        int a = attn[bs * NL + l];
        af[l] = (a != 0) ? 1.0f : 0.0f;
        rm[2 * l] = 0u; rm[2 * l + 1] = 0u;
        if (a != 0) atomicAdd(tokcnt, 1);
    }
    if (tid < NPAIR * NT) {   // 192 == NPAIR*NT exactly
        int arg = tid / (NP * NT);
        int rem = tid % (NP * NT);
        const int* src = (arg == 0) ? pred_ids : ((arg == 1) ? arg0_ids : arg1_ids);
        span_s[tid] = src[bs * NP * NT + rem];
    }
    __syncthreads();

    // ---- phase 1: match counts ----
    for (int e = tid; e < NPAIR * NL; e += NTHREADS) {
        int pair = e >> 8;
        int l    = e & (NL - 1);
        int c = 0;
        if (af[l] != 0.0f) {
            int sid = sid_s[l];
            #pragma unroll
            for (int t = 0; t < NT; t++) {
                int v = span_s[pair * NT + t];
                c += (v == sid && v != PAD_ID) ? 1 : 0;
            }
        }
        cnt_s[pair * NL + l] = (unsigned char)c;
        if (c) {
            atomicOr(&rm[2 * l + (pair >> 5)], 1u << (pair & 31));
            atomicAdd(&den_s[pair], c);
        }
    }
    __syncthreads();

    // ---- phase 2: stream 256 x 192 slice, 8 rows per batch ----
    // Cooperative float4 loads: per batch, 8 rows x 48 float4 = 384 LDG.128,
    // 2 per thread. Thread t loads (row = t/24 [+4 for the 2nd], f4 = t%24,
    // and the other 24-group half): flat index i in [0,384): row=i/48, f4=i%48.
    const float* ebase = emb + (size_t)bs * NL * ND + dbase;
    float sacc = 0.0f;

    for (int l0 = 0; l0 < NL; l0 += 8) {
        // load 8x192 subtile into registers as float4, 2 per thread
        float4 va, vb;
        {
            int ia = tid;            // 0..191  -> row ia/48? no: 192 threads, 384 f4 slots
            int ib = tid + NTHREADS; // 192..383
            int ra = ia / 48, fa = ia % 48;
            int rb = ib / 48, fb = ib % 48;
            va = *(const float4*)(ebase + (size_t)(l0 + ra) * ND + fa * 4);
            vb = *(const float4*)(ebase + (size_t)(l0 + rb) * ND + fb * 4);
            __syncthreads();  // stage reuse from previous iteration done
            *(float4*)(stage + ra * DCOLS + fa * 4) = va;
            *(float4*)(stage + rb * DCOLS + fb * 4) = vb;
            __syncthreads();
        }

        #pragma unroll
        for (int k = 0; k < 8; k++) {
            int l = l0 + k;
            float v = stage[k * DCOLS + tid];
            sacc = fmaf(af[l], v, sacc);
            unsigned w0 = rm[2 * l];
            unsigned w1 = rm[2 * l + 1];
            while (w0) {
                int pr = __ffs(w0) - 1; w0 &= (w0 - 1);
                acc[pr * DCOLS + tid] = fmaf((float)cnt_s[pr * NL + l], v, acc[pr * DCOLS + tid]);
            }
            while (w1) {
                int pr = __ffs(w1) - 1; w1 &= (w1 - 1);
                int pp = pr + 32;
                acc[pp * DCOLS + tid] = fmaf((float)cnt_s[pp * NL + l], v, acc[pp * DCOLS + tid]);
            }
        }
    }

    // ---- epilogue ----
    float tc = fmaxf((float)tokcnt[0], 1.0f);
    out[(size_t)bs * ND + dbase + tid] = sacc / tc;

    float* outp = out + (size_t)NB * NS * ND;
    #pragma unroll 4
    for (int pair = 0; pair < NPAIR; pair++) {
        int arg = pair >> 4;
        int p   = pair & 15;
        int den = den_s[pair];
        float val = (den > 0) ? acc[pair * DCOLS + tid] / (float)den : 0.0f;
        size_t off = (size_t)arg * NB * NS * NP * ND
                   + (size_t)bs * NP * ND
                   + (size_t)p * ND + dbase + tid;
        outp[off] = val;
    }
}

extern "C" void kernel_launch(void* const* d_in, const int* in_sizes, int n_in,
                              void* d_out, int out_size)
{
    const int*   sent_ids = (const int*)d_in[0];
    const int*   attn     = (const int*)d_in[1];
    const int*   pred_ids = (const int*)d_in[2];
    const int*   arg0_ids = (const int*)d_in[3];
    const int*   arg1_ids = (const int*)d_in[4];
    const float* emb      = (const float*)d_in[5];
    float*       out      = (float*)d_out;

    cudaFuncSetAttribute(srl_kernel, cudaFuncAttributeMaxDynamicSharedMemorySize, SMEM_BYTES);

    dim3 grid(NB * NS * NSPLIT);
    dim3 block(NTHREADS);
    srl_kernel<<<grid, block, SMEM_BYTES>>>(sent_ids, attn, pred_ids, arg0_ids,
                                            arg1_ids, emb, out);
}

// round 3
// speedup vs baseline: 1.7254x; 1.7254x over previous
#include <cuda_runtime.h>

// SRLEmbeddings: B=16,S=32,L=256,D=768,P=16,T=4, PAD=1
// One CTA per (b,s); 768 threads, thread tid owns output column d=tid.
// Phase 1: build compact per-pair match-event lists (deterministic order).
// Phase 2: pure streaming pass for the sentence average (max MLP, no barriers).
// Phase 3: per pair, gather its few matched rows (L2-hot) into a register.

#define NB 16
#define NS 32
#define NL 256
#define ND 768
#define NP 16
#define NT 4
#define NPAIR 48
#define PAD_ID 1
#define NTHREADS 768

// smem layout (bytes):
//   events : NPAIR*NL*4 = 49152   (packed: l | cnt<<16)
//   sid_s  : NL*4       = 1024
//   af     : NL*4       = 1024
//   span_s : NPAIR*NT*4 = 768
//   nev    : NPAIR*4    = 192
//   tokcnt : 16
#define SMEM_BYTES (49152 + 1024 + 1024 + 768 + 192 + 16)

__global__ __launch_bounds__(NTHREADS, 2)
void srl_kernel(const int* __restrict__ sent_ids,
                const int* __restrict__ attn,
                const int* __restrict__ pred_ids,
                const int* __restrict__ arg0_ids,
                const int* __restrict__ arg1_ids,
                const float* __restrict__ emb,
                float* __restrict__ out)
{
    extern __shared__ char smem_raw[];
    unsigned* events = (unsigned*)smem_raw;            // [NPAIR][NL]
    int*      sid_s  = (int*)(events + NPAIR * NL);    // [NL]
    float*    af     = (float*)(sid_s + NL);           // [NL]
    int*      span_s = (int*)(af + NL);                // [NPAIR][NT]
    int*      nev    = (int*)(span_s + NPAIR * NT);    // [NPAIR]
    int*      tokcnt = nev + NPAIR;

    const int bs  = blockIdx.x;     // b*NS + s
    const int tid = threadIdx.x;    // 0..767 == column d

    // ---- load per-(b,s) metadata ----
    if (tid == 0) tokcnt[0] = 0;
    if (tid < NL) {
        sid_s[tid] = sent_ids[bs * NL + tid];
        int a = attn[bs * NL + tid];
        af[tid] = (a != 0) ? 1.0f : 0.0f;
        if (a != 0) atomicAdd(tokcnt, 1);
    }
    if (tid < NPAIR * NT) {         // 192 ints
        int arg = tid / (NP * NT);
        int rem = tid % (NP * NT);
        const int* src = (arg == 0) ? pred_ids : ((arg == 1) ? arg0_ids : arg1_ids);
        span_s[tid] = src[bs * NP * NT + rem];
    }
    __syncthreads();

    // ---- phase 1: one thread per pair builds its event list (deterministic) ----
    if (tid < NPAIR) {
        int v0 = span_s[tid * NT + 0];
        int v1 = span_s[tid * NT + 1];
        int v2 = span_s[tid * NT + 2];
        int v3 = span_s[tid * NT + 3];
        int n = 0;
        #pragma unroll 4
        for (int l = 0; l < NL; l++) {
            if (af[l] != 0.0f) {
                int sid = sid_s[l];
                int c = (v0 == sid && v0 != PAD_ID)
                      + (v1 == sid && v1 != PAD_ID)
                      + (v2 == sid && v2 != PAD_ID)
                      + (v3 == sid && v3 != PAD_ID);
                if (c) {
                    events[tid * NL + n] = (unsigned)l | ((unsigned)c << 16);
                    n++;
                }
            }
        }
        nev[tid] = n;
    }
    __syncthreads();

    // ---- phase 2: pure streaming pass for the sentence sum ----
    const float* ebase = emb + (size_t)bs * NL * ND + tid;
    float sacc = 0.0f;

    #pragma unroll 1
    for (int l0 = 0; l0 < NL; l0 += 16) {
        float v[16];
        #pragma unroll
        for (int k = 0; k < 16; k++)
            v[k] = __ldg(ebase + (size_t)(l0 + k) * ND);
        #pragma unroll
        for (int k = 0; k < 16; k++)
            sacc = fmaf(af[l0 + k], v[k], sacc);
    }

    float tc = fmaxf((float)tokcnt[0], 1.0f);
    out[(size_t)bs * ND + tid] = sacc / tc;

    // ---- phase 3: per-pair gather of matched rows (L2-resident) ----
    float* outp = out + (size_t)NB * NS * ND;
    const float* embs = emb + (size_t)bs * NL * ND + tid;

    #pragma unroll 1
    for (int pair = 0; pair < NPAIR; pair++) {
        int ne = nev[pair];
        float val = 0.0f;
        int   den = 0;
        for (int i = 0; i < ne; i++) {
            unsigned e = events[pair * NL + i];
            int l = (int)(e & 0xFFFFu);
            int c = (int)(e >> 16);
            den += c;
            val = fmaf((float)c, __ldg(embs + (size_t)l * ND), val);
        }
        float o = (den > 0) ? val / (float)den : 0.0f;

        int arg = pair >> 4;
        int p   = pair & 15;
        size_t off = (size_t)arg * NB * NS * NP * ND
                   + (size_t)bs * NP * ND
                   + (size_t)p * ND + tid;
        outp[off] = o;
    }
}

extern "C" void kernel_launch(void* const* d_in, const int* in_sizes, int n_in,
                              void* d_out, int out_size)
{
    const int*   sent_ids = (const int*)d_in[0];
    const int*   attn     = (const int*)d_in[1];
    const int*   pred_ids = (const int*)d_in[2];
    const int*   arg0_ids = (const int*)d_in[3];
    const int*   arg1_ids = (const int*)d_in[4];
    const float* emb      = (const float*)d_in[5];
    float*       out      = (float*)d_out;

    cudaFuncSetAttribute(srl_kernel, cudaFuncAttributeMaxDynamicSharedMemorySize, SMEM_BYTES);

    dim3 grid(NB * NS);
    dim3 block(NTHREADS);
    srl_kernel<<<grid, block, SMEM_BYTES>>>(sent_ids, attn, pred_ids, arg0_ids,
                                            arg1_ids, emb, out);
}

// round 4
// speedup vs baseline: 1.9024x; 1.1026x over previous
#include <cuda_runtime.h>

// SRLEmbeddings: B=16,S=32,L=256,D=768,P=16,T=4, PAD=1
// One CTA per (b,s); 768 threads, thread tid owns output column d=tid.
// Key insight: rows with attn==0 contribute to NOTHING (sentence avg is
// mask-weighted; span matches require attn!=0). Only stream active rows (~50%).

#define NB 16
#define NS 32
#define NL 256
#define ND 768
#define NP 16
#define NT 4
#define NPAIR 48
#define PAD_ID 1
#define NTHREADS 768

// smem layout (bytes):
//   events : NPAIR*NL*4 = 49152   (packed: l | cnt<<16)
//   alist  : NL*4       = 1024    (active row indices, ascending)
//   sid_s  : NL*4       = 1024
//   span_s : NPAIR*NT*4 = 768
//   nev    : NPAIR*4    = 192
//   nact   : 16
#define SMEM_BYTES (49152 + 1024 + 1024 + 768 + 192 + 16)

__global__ __launch_bounds__(NTHREADS, 2)
void srl_kernel(const int* __restrict__ sent_ids,
                const int* __restrict__ attn,
                const int* __restrict__ pred_ids,
                const int* __restrict__ arg0_ids,
                const int* __restrict__ arg1_ids,
                const float* __restrict__ emb,
                float* __restrict__ out)
{
    extern __shared__ char smem_raw[];
    unsigned* events = (unsigned*)smem_raw;            // [NPAIR][NL]
    int*      alist  = (int*)(events + NPAIR * NL);    // [NL]
    int*      sid_s  = (int*)(alist + NL);             // [NL]
    int*      span_s = (int*)(sid_s + NL);             // [NPAIR][NT]
    int*      nev    = (int*)(span_s + NPAIR * NT);    // [NPAIR]
    int*      nact_s = nev + NPAIR;

    const int bs   = blockIdx.x;    // b*NS + s
    const int tid  = threadIdx.x;   // 0..767 == column d
    const int lane = tid & 31;

    // ---- load sentence ids ----
    if (tid < NL) sid_s[tid] = sent_ids[bs * NL + tid];
    if (tid < NPAIR * NT) {         // 192 ints
        int arg = tid / (NP * NT);
        int rem = tid % (NP * NT);
        const int* src = (arg == 0) ? pred_ids : ((arg == 1) ? arg0_ids : arg1_ids);
        span_s[tid] = src[bs * NP * NT + rem];
    }

    // ---- warp 0: build compact active-row list (ascending, deterministic) ----
    if (tid < 32) {
        int base = 0;
        #pragma unroll
        for (int c = 0; c < NL / 32; c++) {
            int l = c * 32 + lane;
            int a = attn[bs * NL + l];
            unsigned m = __ballot_sync(0xFFFFFFFFu, a != 0);
            if (a != 0) {
                int pos = base + __popc(m & ((1u << lane) - 1u));
                alist[pos] = l;
            }
            base += __popc(m);
        }
        if (lane == 0) nact_s[0] = base;
    }
    __syncthreads();

    const int nact = nact_s[0];

    // ---- phase 1: one thread per pair builds its event list ----
    if (tid < NPAIR) {
        int v0 = span_s[tid * NT + 0];
        int v1 = span_s[tid * NT + 1];
        int v2 = span_s[tid * NT + 2];
        int v3 = span_s[tid * NT + 3];
        int n = 0;
        for (int i = 0; i < nact; i++) {
            int l = alist[i];
            int sid = sid_s[l];
            int c = (v0 == sid && v0 != PAD_ID)
                  + (v1 == sid && v1 != PAD_ID)
                  + (v2 == sid && v2 != PAD_ID)
                  + (v3 == sid && v3 != PAD_ID);
            if (c) {
                events[tid * NL + n] = (unsigned)l | ((unsigned)c << 16);
                n++;
            }
        }
        nev[tid] = n;
    }
    __syncthreads();

    // ---- phase 2: stream ACTIVE rows only (pure: LDG + ADD) ----
    const float* ebase = emb + (size_t)bs * NL * ND + tid;
    float sacc = 0.0f;

    #pragma unroll 1
    for (int i0 = 0; i0 < nact; i0 += 8) {
        float v[8];
        #pragma unroll
        for (int k = 0; k < 8; k++) {
            int idx = i0 + k;
            int cidx = (idx < nact) ? idx : (nact - 1);   // clamped (safe re-read)
            int l = alist[cidx];
            v[k] = __ldg(ebase + (size_t)l * ND);
            if (idx >= nact) v[k] = 0.0f;
        }
        #pragma unroll
        for (int k = 0; k < 8; k++) sacc += v[k];
    }

    float tc = fmaxf((float)nact, 1.0f);
    out[(size_t)bs * ND + tid] = sacc / tc;

    // ---- phase 3: per-pair gather, 4-wide predicated chunks (L2-hot) ----
    float* outp = out + (size_t)NB * NS * ND;

    #pragma unroll 1
    for (int pair = 0; pair < NPAIR; pair++) {
        int ne = nev[pair];
        float val = 0.0f;
        int   den = 0;
        #pragma unroll 1
        for (int i = 0; i < ne; i += 4) {
            float v[4]; int c[4];
            #pragma unroll
            for (int k = 0; k < 4; k++) {
                int idx = i + k;
                bool ok = idx < ne;
                unsigned e = events[pair * NL + (ok ? idx : 0)];
                int l = (int)(e & 0xFFFFu);
                c[k] = ok ? (int)(e >> 16) : 0;
                v[k] = ok ? __ldg(ebase + (size_t)l * ND) : 0.0f;
            }
            #pragma unroll
            for (int k = 0; k < 4; k++) {
                val = fmaf((float)c[k], v[k], val);
                den += c[k];
            }
        }
        float o = (den > 0) ? val / (float)den : 0.0f;

        int arg = pair >> 4;
        int p   = pair & 15;
        size_t off = (size_t)arg * NB * NS * NP * ND
                   + (size_t)bs * NP * ND
                   + (size_t)p * ND + tid;
        outp[off] = o;
    }
}

extern "C" void kernel_launch(void* const* d_in, const int* in_sizes, int n_in,
                              void* d_out, int out_size)
{
    const int*   sent_ids = (const int*)d_in[0];
    const int*   attn     = (const int*)d_in[1];
    const int*   pred_ids = (const int*)d_in[2];
    const int*   arg0_ids = (const int*)d_in[3];
    const int*   arg1_ids = (const int*)d_in[4];
    const float* emb      = (const float*)d_in[5];
    float*       out      = (float*)d_out;

    cudaFuncSetAttribute(srl_kernel, cudaFuncAttributeMaxDynamicSharedMemorySize, SMEM_BYTES);

    dim3 grid(NB * NS);
    dim3 block(NTHREADS);
    srl_kernel<<<grid, block, SMEM_BYTES>>>(sent_ids, attn, pred_ids, arg0_ids,
                                            arg1_ids, emb, out);
}

// round 5
// speedup vs baseline: 2.9283x; 1.5392x over previous
#include <cuda_runtime.h>

// SRLEmbeddings: B=16,S=32,L=256,D=768,P=16,T=4, PAD=1
// One CTA per (b,s). 768 threads as (cg = tid%192 owning cols 4cg..4cg+3,
// rl = tid/192 row-lane). All embedding traffic is LDG.128 / STG.128.
// Phase 1 (48 threads, overlapped with phase 2): per-pair match-event lists.
// Phase 2: stream active rows only; per-rowlane partial sentence sums.
// Phase 3: per-pair gather of matched rows (L2-hot), rowlane-partitioned.

#define NB 16
#define NS 32
#define NL 256
#define ND 768
#define ND4 (ND / 4)
#define NP 16
#define NT 4
#define NPAIR 48
#define PAD_ID 1
#define NTHREADS 768
#define NCG 192

// smem (bytes): events 49152 | stage 12288 | alist 1024 | sid 1024 | span 768 | nev 192 | nact 16
#define SMEM_BYTES (49152 + 12288 + 1024 + 1024 + 768 + 192 + 16)

__global__ __launch_bounds__(NTHREADS, 2)
void srl_kernel(const int* __restrict__ sent_ids,
                const int* __restrict__ attn,
                const int* __restrict__ pred_ids,
                const int* __restrict__ arg0_ids,
                const int* __restrict__ arg1_ids,
                const float* __restrict__ emb,
                float* __restrict__ out)
{
    extern __shared__ char smem_raw[];
    unsigned* events = (unsigned*)smem_raw;               // [NPAIR][NL]  (l | cnt<<16)
    float4*   stage  = (float4*)(events + NPAIR * NL);    // [4][NCG]
    int*      alist  = (int*)(stage + 4 * NCG);           // [NL]
    int*      sid_s  = alist + NL;                        // [NL]
    int*      span_s = sid_s + NL;                        // [NPAIR][NT]
    int*      nev    = span_s + NPAIR * NT;               // [NPAIR]
    int*      nact_s = nev + NPAIR;

    const int bs   = blockIdx.x;
    const int tid  = threadIdx.x;
    const int lane = tid & 31;
    const int cg   = tid % NCG;     // column group: cols [4cg, 4cg+3]
    const int rl   = tid / NCG;     // row lane 0..3

    // ---- metadata ----
    if (tid < NL) sid_s[tid] = sent_ids[bs * NL + tid];
    if (tid < NPAIR * NT) {         // 192 ints
        int arg = tid / (NP * NT);
        int rem = tid % (NP * NT);
        const int* src = (arg == 0) ? pred_ids : ((arg == 1) ? arg0_ids : arg1_ids);
        span_s[tid] = src[bs * NP * NT + rem];
    }
    // warp 0: compact active-row list (ascending)
    if (tid < 32) {
        int base = 0;
        #pragma unroll
        for (int c = 0; c < NL / 32; c++) {
            int l = c * 32 + lane;
            int a = attn[bs * NL + l];
            unsigned m = __ballot_sync(0xFFFFFFFFu, a != 0);
            if (a != 0) alist[base + __popc(m & ((1u << lane) - 1u))] = l;
            base += __popc(m);
        }
        if (lane == 0) nact_s[0] = base;
    }
    __syncthreads();

    const int nact = nact_s[0];

    // ---- phase 1 (48 threads; overlaps phase 2 of the other warps) ----
    if (tid < NPAIR) {
        int v0 = span_s[tid * NT + 0];
        int v1 = span_s[tid * NT + 1];
        int v2 = span_s[tid * NT + 2];
        int v3 = span_s[tid * NT + 3];
        int n = 0;
        for (int i = 0; i < nact; i++) {
            int l = alist[i];
            int sid = sid_s[l];
            int c = (v0 == sid && v0 != PAD_ID)
                  + (v1 == sid && v1 != PAD_ID)
                  + (v2 == sid && v2 != PAD_ID)
                  + (v3 == sid && v3 != PAD_ID);
            if (c) events[tid * NL + (n++)] = (unsigned)l | ((unsigned)c << 16);
        }
        nev[tid] = n;
    }

    // ---- phase 2: stream active rows, 16 rows/batch, 4 float4 per thread ----
    const float4* ebase = (const float4*)(emb + (size_t)bs * NL * ND) + cg;
    float4 s4 = make_float4(0.f, 0.f, 0.f, 0.f);
    const int clampi = nact - 1;

    #pragma unroll 1
    for (int i0 = 0; i0 < nact; i0 += 16) {
        float4 v[4];
        int    idx[4];
        #pragma unroll
        for (int k = 0; k < 4; k++) {
            idx[k] = i0 + 4 * k + rl;
            int ci = min(idx[k], clampi);
            int l  = alist[ci];
            v[k] = __ldg(ebase + (size_t)l * ND4);
        }
        #pragma unroll
        for (int k = 0; k < 4; k++) {
            if (idx[k] < nact) {
                s4.x += v[k].x; s4.y += v[k].y; s4.z += v[k].z; s4.w += v[k].w;
            }
        }
    }
    stage[rl * NCG + cg] = s4;
    __syncthreads();    // orders: stage writes AND phase-1 event writes

    // ---- sentence average (rowlane 0 stores float4) ----
    if (rl == 0) {
        float4 a = stage[cg], b = stage[NCG + cg];
        float4 c = stage[2 * NCG + cg], d = stage[3 * NCG + cg];
        float tc = fmaxf((float)nact, 1.0f);
        float4 o;
        o.x = (a.x + b.x + c.x + d.x) / tc;
        o.y = (a.y + b.y + c.y + d.y) / tc;
        o.z = (a.z + b.z + c.z + d.z) / tc;
        o.w = (a.w + b.w + c.w + d.w) / tc;
        ((float4*)(out + (size_t)bs * ND))[cg] = o;
    }

    // ---- phase 3: pairs partitioned by rowlane (12 each), float4 gathers ----
    float* outp = out + (size_t)NB * NS * ND;

    #pragma unroll 1
    for (int j = 0; j < NPAIR / 4; j++) {
        int pair = j * 4 + rl;
        int ne   = nev[pair];
        float4 val = make_float4(0.f, 0.f, 0.f, 0.f);
        int den = 0;
        #pragma unroll 1
        for (int i = 0; i < ne; i += 2) {
            unsigned e0 = events[pair * NL + i];
            bool ok1 = (i + 1) < ne;
            unsigned e1 = events[pair * NL + (ok1 ? i + 1 : i)];
            int l0 = (int)(e0 & 0xFFFFu); float c0 = (float)(e0 >> 16);
            int l1 = (int)(e1 & 0xFFFFu); float c1 = ok1 ? (float)(e1 >> 16) : 0.0f;
            float4 w0 = __ldg(ebase + (size_t)l0 * ND4);
            float4 w1 = __ldg(ebase + (size_t)l1 * ND4);
            val.x = fmaf(c0, w0.x, fmaf(c1, w1.x, val.x));
            val.y = fmaf(c0, w0.y, fmaf(c1, w1.y, val.y));
            val.z = fmaf(c0, w0.z, fmaf(c1, w1.z, val.z));
            val.w = fmaf(c0, w0.w, fmaf(c1, w1.w, val.w));
            den += (int)c0 + (int)c1;
        }
        float inv = (den > 0) ? 1.0f / (float)den : 0.0f;
        float4 o = make_float4(val.x * inv, val.y * inv, val.z * inv, val.w * inv);

        int arg = pair >> 4;
        int p   = pair & 15;
        size_t off = (size_t)arg * NB * NS * NP * ND
                   + (size_t)bs * NP * ND
                   + (size_t)p * ND;
        ((float4*)(outp + off))[cg] = o;
    }
}

extern "C" void kernel_launch(void* const* d_in, const int* in_sizes, int n_in,
                              void* d_out, int out_size)
{
    const int*   sent_ids = (const int*)d_in[0];
    const int*   attn     = (const int*)d_in[1];
    const int*   pred_ids = (const int*)d_in[2];
    const int*   arg0_ids = (const int*)d_in[3];
    const int*   arg1_ids = (const int*)d_in[4];
    const float* emb      = (const float*)d_in[5];
    float*       out      = (float*)d_out;

    cudaFuncSetAttribute(srl_kernel, cudaFuncAttributeMaxDynamicSharedMemorySize, SMEM_BYTES);

    dim3 grid(NB * NS);
    dim3 block(NTHREADS);
    srl_kernel<<<grid, block, SMEM_BYTES>>>(sent_ids, attn, pred_ids, arg0_ids,
                                            arg1_ids, emb, out);
}

// round 6
// speedup vs baseline: 3.7396x; 1.2771x over previous
#include <cuda_runtime.h>

// SRLEmbeddings: B=16,S=32,L=256,D=768,P=16,T=4, PAD=1
// One CTA per (b,s), 384 threads = 192 col-groups x 2 row-lanes.
// __launch_bounds__(384,4): 4 CTAs/SM -> all 512 CTAs resident in ONE wave.
// Phase 1 (48 threads): per-pair match-event lists (uint16 packed).
// Phase 2: stream active rows only; LDG.128, 4 in flight per thread.
// Phase 3: per-pair gather of matched rows, 4 events in flight.

#define NB 16
#define NS 32
#define NL 256
#define ND 768
#define ND4 (ND / 4)
#define NP 16
#define NT 4
#define NPAIR 48
#define PAD_ID 1
#define NTHREADS 384
#define NCG 192
#define NRL 2

// smem (bytes): events(u16) 24576 | stage 6144 | alist 1024 | sid 1024 | span 768 | nev 192 | nact 16
#define SMEM_BYTES (24576 + 6144 + 1024 + 1024 + 768 + 192 + 16)

__global__ __launch_bounds__(NTHREADS, 4)
void srl_kernel(const int* __restrict__ sent_ids,
                const int* __restrict__ attn,
                const int* __restrict__ pred_ids,
                const int* __restrict__ arg0_ids,
                const int* __restrict__ arg1_ids,
                const float* __restrict__ emb,
                float* __restrict__ out)
{
    extern __shared__ char smem_raw[];
    unsigned short* events = (unsigned short*)smem_raw;      // [NPAIR][NL]  (l | cnt<<8)
    float4* stage  = (float4*)(events + NPAIR * NL);         // [NRL][NCG]
    int*    alist  = (int*)(stage + NRL * NCG);              // [NL]
    int*    sid_s  = alist + NL;                             // [NL]
    int*    span_s = sid_s + NL;                             // [NPAIR][NT]
    int*    nev    = span_s + NPAIR * NT;                    // [NPAIR]
    int*    nact_s = nev + NPAIR;

    const int bs   = blockIdx.x;
    const int tid  = threadIdx.x;
    const int lane = tid & 31;
    const int cg   = tid % NCG;     // column group: cols [4cg, 4cg+3]
    const int rl   = tid / NCG;     // row lane 0..1

    // ---- metadata ----
    if (tid < NL) sid_s[tid] = sent_ids[bs * NL + tid];
    {   // span ids: 192 ints over 384 threads (first 192 do it)
        if (tid < NPAIR * NT) {
            int arg = tid / (NP * NT);
            int rem = tid % (NP * NT);
            const int* src = (arg == 0) ? pred_ids : ((arg == 1) ? arg0_ids : arg1_ids);
            span_s[tid] = src[bs * NP * NT + rem];
        }
    }
    // warp 0: compact active-row list (ascending, deterministic)
    if (tid < 32) {
        int base = 0;
        #pragma unroll
        for (int c = 0; c < NL / 32; c++) {
            int l = c * 32 + lane;
            int a = attn[bs * NL + l];
            unsigned m = __ballot_sync(0xFFFFFFFFu, a != 0);
            if (a != 0) alist[base + __popc(m & ((1u << lane) - 1u))] = l;
            base += __popc(m);
        }
        if (lane == 0) nact_s[0] = base;
    }
    __syncthreads();

    const int nact = nact_s[0];

    // ---- phase 1 (48 threads; overlaps phase 2 of the other warps) ----
    if (tid < NPAIR) {
        int v0 = span_s[tid * NT + 0];
        int v1 = span_s[tid * NT + 1];
        int v2 = span_s[tid * NT + 2];
        int v3 = span_s[tid * NT + 3];
        int n = 0;
        for (int i = 0; i < nact; i++) {
            int l = alist[i];
            int sid = sid_s[l];
            int c = (v0 == sid && v0 != PAD_ID)
                  + (v1 == sid && v1 != PAD_ID)
                  + (v2 == sid && v2 != PAD_ID)
                  + (v3 == sid && v3 != PAD_ID);
            if (c) events[tid * NL + (n++)] = (unsigned short)(l | (c << 8));
        }
        nev[tid] = n;
    }

    // ---- phase 2: stream active rows; 8-row batches, 4 LDG.128/thread ----
    const float4* ebase = (const float4*)(emb + (size_t)bs * NL * ND) + cg;
    float4 s4 = make_float4(0.f, 0.f, 0.f, 0.f);
    const int clampi = nact - 1;

    #pragma unroll 1
    for (int i0 = 0; i0 < nact; i0 += 8) {
        float4 v[4];
        int    idx[4];
        #pragma unroll
        for (int k = 0; k < 4; k++) {
            idx[k] = i0 + 2 * k + rl;
            int ci = min(idx[k], clampi);
            int l  = alist[ci];
            v[k] = __ldg(ebase + (size_t)l * ND4);
        }
        #pragma unroll
        for (int k = 0; k < 4; k++) {
            if (idx[k] < nact) {
                s4.x += v[k].x; s4.y += v[k].y; s4.z += v[k].z; s4.w += v[k].w;
            }
        }
    }
    stage[rl * NCG + cg] = s4;
    __syncthreads();    // orders: stage writes AND phase-1 event writes

    // ---- sentence average (rowlane 0 stores float4) ----
    if (rl == 0) {
        float4 a = stage[cg], b = stage[NCG + cg];
        float tc = fmaxf((float)nact, 1.0f);
        float4 o;
        o.x = (a.x + b.x) / tc;
        o.y = (a.y + b.y) / tc;
        o.z = (a.z + b.z) / tc;
        o.w = (a.w + b.w) / tc;
        ((float4*)(out + (size_t)bs * ND))[cg] = o;
    }

    // ---- phase 3: pairs split by rowlane (24 each), 4 events in flight ----
    float* outp = out + (size_t)NB * NS * ND;

    #pragma unroll 1
    for (int j = 0; j < NPAIR / NRL; j++) {
        int pair = j * NRL + rl;
        int ne   = nev[pair];
        float4 val = make_float4(0.f, 0.f, 0.f, 0.f);
        int den = 0;
        #pragma unroll 1
        for (int i = 0; i < ne; i += 4) {
            float4 w[4]; float c[4];
            #pragma unroll
            for (int k = 0; k < 4; k++) {
                int idx = i + k;
                bool ok = idx < ne;
                unsigned e = events[pair * NL + (ok ? idx : i)];
                int l = (int)(e & 0xFFu);
                c[k] = ok ? (float)(e >> 8) : 0.0f;
                w[k] = __ldg(ebase + (size_t)l * ND4);
            }
            #pragma unroll
            for (int k = 0; k < 4; k++) {
                val.x = fmaf(c[k], w[k].x, val.x);
                val.y = fmaf(c[k], w[k].y, val.y);
                val.z = fmaf(c[k], w[k].z, val.z);
                val.w = fmaf(c[k], w[k].w, val.w);
                den += (int)c[k];
            }
        }
        float inv = (den > 0) ? 1.0f / (float)den : 0.0f;
        float4 o = make_float4(val.x * inv, val.y * inv, val.z * inv, val.w * inv);

        int arg = pair >> 4;
        int p   = pair & 15;
        size_t off = (size_t)arg * NB * NS * NP * ND
                   + (size_t)bs * NP * ND
                   + (size_t)p * ND;
        ((float4*)(outp + off))[cg] = o;
    }
}

extern "C" void kernel_launch(void* const* d_in, const int* in_sizes, int n_in,
                              void* d_out, int out_size)
{
    const int*   sent_ids = (const int*)d_in[0];
    const int*   attn     = (const int*)d_in[1];
    const int*   pred_ids = (const int*)d_in[2];
    const int*   arg0_ids = (const int*)d_in[3];
    const int*   arg1_ids = (const int*)d_in[4];
    const float* emb      = (const float*)d_in[5];
    float*       out      = (float*)d_out;

    cudaFuncSetAttribute(srl_kernel, cudaFuncAttributeMaxDynamicSharedMemorySize, SMEM_BYTES);

    dim3 grid(NB * NS);
    dim3 block(NTHREADS);
    srl_kernel<<<grid, block, SMEM_BYTES>>>(sent_ids, attn, pred_ids, arg0_ids,
                                            arg1_ids, emb, out);
}